// round 8
// baseline (speedup 1.0000x reference)
#include <cuda_runtime.h>

#define QW   12
#define DIMS 4096
#define NT   256
#define V    16

// Position s (12 bits) per layout: layK(LAY,i) = s-bit of k bit i (4 reg bits),
// layL(LAY,i) = s-bit of lane bit i (5), layW(LAY,i) = s-bit of warp bit i (3).
// wire j <-> s-bit (11-j).
// Layout A(0): K={0,1,2,3}   L={4,5,6,7,8}    W={9,10,11}
// Layout B(1): K={8,9,10,11} L={0,1,2,3,4}    W={5,6,7}
// Layout C(2): K={4,5,6,7}   L={8,9,10,11,0}  W={1,2,3}
// Group: diag -> 4 locals -> T1 (k<->lane0-3, intra-warp) -> 4 locals
//        -> T2 (k<->{lane4,warp}, cross-warp) -> 4 locals.  A->B->C->A cycle.

__host__ __device__ constexpr int layK(int LAY, int i) {
    return LAY == 0 ? i : (LAY == 1 ? 8 + i : 4 + i);
}
__host__ __device__ constexpr int layL(int LAY, int i) {
    return LAY == 0 ? 4 + i : (LAY == 1 ? i : (i < 4 ? 8 + i : 0));
}
__host__ __device__ constexpr int layW(int LAY, int i) {
    return LAY == 0 ? 9 + i : (LAY == 1 ? 5 + i : 1 + i);
}

__device__ __forceinline__ float2 cmulf(float2 a, float2 b) {
    return make_float2(fmaf(a.x, b.x, -a.y * b.y), fmaf(a.x, b.y, a.y * b.x));
}
__device__ __forceinline__ int rotl12(int s, int r) {
    return ((s << r) | (s >> (12 - r))) & 0xFFF;
}

struct Sm {
    float2 xch1[DIMS];       // 32KB: T1 tiles (per-warp 512) / image buffer
    float2 xch2[DIMS];       // 32KB: T2 exchange
    float2 tab[16];
    float2 csT[2][6][12];
    float2 uvT[2][6][12];
    float  aS[2][6][12];
    float  ang[12];
    float  red[8 * 12];
    float  cwS[108];
    float  cbS[12];
};

template<int M>
__device__ __forceinline__ void ry_lift(float2* amp, float2 uv) {
    const float u = uv.x, v = uv.y;
#pragma unroll
    for (int k = 0; k < V; k++) {
        if (!(k & M)) {
            float2 a = amp[k], b = amp[k | M];
            a.x = fmaf(u, b.x, a.x); a.y = fmaf(u, b.y, a.y);
            b.x = fmaf(v, a.x, b.x); b.y = fmaf(v, a.y, b.y);
            a.x = fmaf(u, b.x, a.x); a.y = fmaf(u, b.y, a.y);
            amp[k] = a; amp[k | M] = b;
        }
    }
}

__device__ __forceinline__ void reduce12(Sm& sm, float* part, int t, int lane,
                                         float scale, bool addBias) {
#pragma unroll
    for (int j = 0; j < QW; j++) {
        float v = part[j];
        v += __shfl_down_sync(0xffffffffu, v, 16);
        v += __shfl_down_sync(0xffffffffu, v, 8);
        v += __shfl_down_sync(0xffffffffu, v, 4);
        v += __shfl_down_sync(0xffffffffu, v, 2);
        v += __shfl_down_sync(0xffffffffu, v, 1);
        if (lane == 0) sm.red[(t >> 5) * QW + j] = v;
    }
    __syncthreads();
    if (t < QW) {
        float v = 0.f;
#pragma unroll
        for (int w = 0; w < 8; w++) v += sm.red[w * QW + t];
        v *= scale;
        if (addBias) v += sm.cbS[t];
        sm.ang[t] = v;
    }
    __syncthreads();
}

template<int LAY, int R, bool ADDI, bool FIRST>
__device__ __forceinline__ void do_group(Sm& sm, float2* amp, const float* aSp,
                                         const float2* uv, int t) {
    const int lane = t & 31, w = t >> 5;
    const int l16 = lane & 15, h = (lane >> 4) & 1;

    // ---- tab build (16 entries over k bits; kk CZ parity folded) ----
    if (t < 16) {
        int k = t, km = 0;
        float ph = 0.f;
#pragma unroll
        for (int i = 0; i < 4; i++) {
            const int wi = 11 - layK(LAY, i);
            float a = aSp[wi] + (ADDI ? sm.ang[wi] : 0.f);
            ph += a * ((float)((k >> i) & 1) - 0.5f);
            km |= ((k >> i) & 1) << layK(LAY, i);
        }
        int par = __popc(km & rotl12(km, R)) & 1;
        float sv, cv; __sincosf(ph, &sv, &cv);
        float sg = par ? -1.f : 1.f;
        sm.tab[k] = make_float2(cv * sg, sv * sg);
    }

    // ---- per-thread phase (8 t bits), tt parity, cross mask ----
    float ph = 0.f; int sB = 0;
#pragma unroll
    for (int i = 0; i < 5; i++) {
        const int wi = 11 - layL(LAY, i);
        float a = aSp[wi] + (ADDI ? sm.ang[wi] : 0.f);
        int bit = (t >> i) & 1;
        ph += a * ((float)bit - 0.5f);
        sB |= bit << layL(LAY, i);
    }
#pragma unroll
    for (int i = 0; i < 3; i++) {
        const int wi = 11 - layW(LAY, i);
        float a = aSp[wi] + (ADDI ? sm.ang[wi] : 0.f);
        int bit = (t >> (5 + i)) & 1;
        ph += a * ((float)bit - 0.5f);
        sB |= bit << layW(LAY, i);
    }
    const int ptt = __popc(sB & rotl12(sB, R)) & 1;
    int c = 0;
#pragma unroll
    for (int i = 0; i < 4; i++)
        c |= (((sB >> ((layK(LAY, i) + R) % 12)) ^ (sB >> ((layK(LAY, i) + 12 - R) % 12))) & 1) << i;
    float sv, cv; __sincosf(ph, &sv, &cv);
    if (ptt) { sv = -sv; cv = -cv; }
    const float2 et  = make_float2(cv, sv);
    const float2 net = make_float2(-cv, -sv);
    __syncthreads();   // tab ready; also fences prev group's T2 reads

    // ---- diagonal ----
#pragma unroll
    for (int k = 0; k < V; k++) {
        float2 e = ((0x6996u >> (k & c)) & 1) ? net : et;
        float2 d = cmulf(e, sm.tab[k]);
        if (FIRST) {
            float ax = amp[k].x;
            amp[k] = make_float2(ax * d.x, ax * d.y);
        } else {
            amp[k] = cmulf(amp[k], d);
        }
    }

    // ---- stage 1: gates on current k bits (wires 11-K[i]) ----
    ry_lift<1>(amp, uv[11 - layK(LAY, 0)]);
    ry_lift<2>(amp, uv[11 - layK(LAY, 1)]);
    ry_lift<4>(amp, uv[11 - layK(LAY, 2)]);
    ry_lift<8>(amp, uv[11 - layK(LAY, 3)]);

    // ---- T1: intra-warp 16x16 transpose (k <-> lane bits 0-3) ----
    {
        float2* tile = sm.xch1 + w * 512 + h * 256;
#pragma unroll
        for (int k = 0; k < V; k++) tile[l16 * 16 + (k ^ l16)] = amp[k];
        __syncwarp();
#pragma unroll
        for (int k = 0; k < V; k++) amp[k] = tile[k * 16 + (l16 ^ k)];
        __syncwarp();
    }

    // ---- stage 2: wires 11-L[i], i<4 ----
    ry_lift<1>(amp, uv[11 - layL(LAY, 0)]);
    ry_lift<2>(amp, uv[11 - layL(LAY, 1)]);
    ry_lift<4>(amp, uv[11 - layL(LAY, 2)]);
    ry_lift<8>(amp, uv[11 - layL(LAY, 3)]);

    // ---- T2: cross-warp exchange (k <-> {lane4, warp bits}) ----
    {
        const int X = h | (w << 1);
#pragma unroll
        for (int k = 0; k < V; k++) sm.xch2[X * 256 + l16 * 16 + (k ^ l16)] = amp[k];
        __syncthreads();
#pragma unroll
        for (int k = 0; k < V; k++) amp[k] = sm.xch2[k * 256 + l16 * 16 + (X ^ l16)];
    }

    // ---- stage 3: wires 11-L[4], 11-W[0..2] ----
    ry_lift<1>(amp, uv[11 - layL(LAY, 4)]);
    ry_lift<2>(amp, uv[11 - layW(LAY, 0)]);
    ry_lift<4>(amp, uv[11 - layW(LAY, 1)]);
    ry_lift<8>(amp, uv[11 - layW(LAY, 2)]);
}

__global__ void __launch_bounds__(NT, 2) qiddm_kernel(
    const float* __restrict__ x, const float* __restrict__ conv_w,
    const float* __restrict__ conv_b, const float* __restrict__ w1,
    const float* __restrict__ lin_w, const float* __restrict__ lin_b,
    float* __restrict__ out)
{
    __shared__ Sm sm;
    const int t    = threadIdx.x;
    const int lane = t & 31;
    const int b    = blockIdx.x;

    // ---------------- weight tables ----------------
    if (t < 144) {
        int idx = t;
        int n = idx / 72, r = idx % 72, g = r / 12, w = r % 12;
        int i = g >> 1, l = g & 1;
        int base = (((n * 3 + i) * 2 + l) * 12 + w) * 3;
        float th = w1[base + 1];
        float svv, cvv; __sincosf(0.5f * th, &svv, &cvv);
        sm.csT[n][g][w] = make_float2(cvv, svv);
        sm.uvT[n][g][w] = make_float2(-__tanf(0.25f * th), svv);
        float a = w1[base + 0];
        if (g > 0) {
            int ip = (g - 1) >> 1, lp = (g - 1) & 1;
            a += w1[(((n * 3 + ip) * 2 + lp) * 12 + w) * 3 + 2];
        }
        sm.aS[n][g][w] = a;
    }
    if (t < 108) sm.cwS[t] = conv_w[t];
    if (t < 12)  sm.cbS[t] = conv_b[t];

    float* img = (float*)sm.xch1;
    const float* xb = x + (size_t)b * 1024;
    for (int i = t; i < 1024; i += NT) img[i] = xb[i];
    __syncthreads();

    // ---------------- conv 3x3 s2 p1 + global avg pool (1 pixel/thread) ----------------
    {
        float acc[QW];
#pragma unroll
        for (int cch = 0; cch < QW; cch++) acc[cch] = 0.f;
        const int oh = t >> 4, ow = t & 15;
#pragma unroll
        for (int kh = 0; kh < 3; kh++) {
            int r2 = 2 * oh + kh - 1;
            if ((unsigned)r2 < 32u) {
#pragma unroll
                for (int kw = 0; kw < 3; kw++) {
                    int c2 = 2 * ow + kw - 1;
                    if ((unsigned)c2 < 32u) {
                        float v = img[r2 * 32 + c2];
#pragma unroll
                        for (int cch = 0; cch < QW; cch++)
                            acc[cch] = fmaf(sm.cwS[cch * 9 + kh * 3 + kw], v, acc[cch]);
                    }
                }
            }
        }
        __syncthreads();
        reduce12(sm, acc, t, lane, 1.f / 256.f, true);
    }

    // ---------------- circuit blocks ----------------
    float2 amp[V];
    for (int n = 0; n < 2; n++) {
        // g=0 skipped: diag on |0> = global phase; 12 RYs on |0> = real product state (layout A)
        const float2* cs0 = sm.csT[n][0];
        // thread factor: lane bit i -> wire 7-i ; warp bit i -> wire 2-i
        float tpp = 1.f;
#pragma unroll
        for (int i = 0; i < 5; i++) tpp *= ((t >> i) & 1) ? cs0[7 - i].y : cs0[7 - i].x;
#pragma unroll
        for (int i = 0; i < 3; i++) tpp *= ((t >> (5 + i)) & 1) ? cs0[2 - i].y : cs0[2 - i].x;
        // k factor: k bit i -> wire 11-i
#pragma unroll
        for (int k = 0; k < V; k++) {
            float p = tpp;
            p *= (k & 1) ? cs0[11].y : cs0[11].x;
            p *= (k & 2) ? cs0[10].y : cs0[10].x;
            p *= (k & 4) ? cs0[9].y  : cs0[9].x;
            p *= (k & 8) ? cs0[8].y  : cs0[8].x;
            amp[k] = make_float2(p, 0.f);
        }

        // groups g=1..5: layouts A,B,C,A,B ; R = CZ ring of prev sublayer ; enc at g=2,4
        do_group<0, 1, false, true >(sm, amp, sm.aS[n][1], sm.uvT[n][1], t);
        do_group<1, 2, true,  false>(sm, amp, sm.aS[n][2], sm.uvT[n][2], t);
        do_group<2, 1, false, false>(sm, amp, sm.aS[n][3], sm.uvT[n][3], t);
        do_group<0, 2, true,  false>(sm, amp, sm.aS[n][4], sm.uvT[n][4], t);
        do_group<1, 1, false, false>(sm, amp, sm.aS[n][5], sm.uvT[n][5], t);

        // ---- measurement in layout C: k bit i -> wire 7-i,
        //      lane bits -> wires {3,2,1,0,11}, warp bits -> wires {10,9,8} ----
        {
            float S = 0.f, q0 = 0.f, q1 = 0.f, q2 = 0.f, q3 = 0.f;
#pragma unroll
            for (int k = 0; k < V; k++) {
                float pr = fmaf(amp[k].x, amp[k].x, amp[k].y * amp[k].y);
                S += pr;
                q0 += (k & 1) ? -pr : pr;
                q1 += (k & 2) ? -pr : pr;
                q2 += (k & 4) ? -pr : pr;
                q3 += (k & 8) ? -pr : pr;
            }
            float part[QW];
            part[7] = q0; part[6] = q1; part[5] = q2; part[4] = q3;
            part[3]  = (t & 1)   ? -S : S;   // lane0 -> wire 3
            part[2]  = (t & 2)   ? -S : S;   // lane1 -> wire 2
            part[1]  = (t & 4)   ? -S : S;   // lane2 -> wire 1
            part[0]  = (t & 8)   ? -S : S;   // lane3 -> wire 0
            part[11] = (t & 16)  ? -S : S;   // lane4 -> wire 11
            part[10] = (t & 32)  ? -S : S;   // warp0 -> wire 10
            part[9]  = (t & 64)  ? -S : S;   // warp1 -> wire 9
            part[8]  = (t & 128) ? -S : S;   // warp2 -> wire 8
            __syncthreads();
            reduce12(sm, part, t, lane, 1.f, false);
        }
    }

    // ---------------- linear head ----------------
#pragma unroll
    for (int q = 0; q < 4; q++) {
        int m = t + q * NT;
        float acc = lin_b[m];
#pragma unroll
        for (int j = 0; j < QW; j++) acc = fmaf(sm.ang[j], lin_w[m * 12 + j], acc);
        out[(size_t)b * 1024 + m] = acc;
    }
}

extern "C" void kernel_launch(void* const* d_in, const int* in_sizes, int n_in,
                              void* d_out, int out_size) {
    const float* x      = (const float*)d_in[0];
    const float* conv_w = (const float*)d_in[1];
    const float* conv_b = (const float*)d_in[2];
    const float* w1     = (const float*)d_in[3];
    const float* lin_w  = (const float*)d_in[4];
    const float* lin_b  = (const float*)d_in[5];
    float* out = (float*)d_out;
    int B = in_sizes[0] / 1024;
    qiddm_kernel<<<B, NT>>>(x, conv_w, conv_b, w1, lin_w, lin_b, out);
}

// round 9
// speedup vs baseline: 1.1341x; 1.1341x over previous
#include <cuda_runtime.h>

#define QW   12
#define DIMS 4096
#define NT   256
#define V    16

typedef unsigned long long ull;

// Position s (12 bits) per layout: layK(LAY,i) = s-bit of k bit i (4 reg bits),
// layL(LAY,i) = s-bit of lane bit i (5), layW(LAY,i) = s-bit of warp bit i (3).
// wire j <-> s-bit (11-j).
// Layout A(0): K={0,1,2,3}   L={4,5,6,7,8}    W={9,10,11}
// Layout B(1): K={8,9,10,11} L={0,1,2,3,4}    W={5,6,7}
// Layout C(2): K={4,5,6,7}   L={8,9,10,11,0}  W={1,2,3}
// Group: diag -> 4 locals -> T1 (k<->lane0-3, intra-warp) -> 4 locals
//        -> T2 (k<->{lane4,warp}, cross-warp) -> 4 locals.  A->B->C->A cycle.

__host__ __device__ constexpr int layK(int LAY, int i) {
    return LAY == 0 ? i : (LAY == 1 ? 8 + i : 4 + i);
}
__host__ __device__ constexpr int layL(int LAY, int i) {
    return LAY == 0 ? 4 + i : (LAY == 1 ? i : (i < 4 ? 8 + i : 0));
}
__host__ __device__ constexpr int layW(int LAY, int i) {
    return LAY == 0 ? 9 + i : (LAY == 1 ? 5 + i : 1 + i);
}

// ---- packed f32x2 helpers (Blackwell FFMA2 path) ----
__device__ __forceinline__ ull pk2(float x, float y) {
    ull r;
    asm("mov.b64 %0, {%1, %2};" : "=l"(r) : "r"(__float_as_uint(x)), "r"(__float_as_uint(y)));
    return r;
}
__device__ __forceinline__ void upk2(ull a, float& x, float& y) {
    unsigned int lo, hi;
    asm("mov.b64 {%0, %1}, %2;" : "=r"(lo), "=r"(hi) : "l"(a));
    x = __uint_as_float(lo); y = __uint_as_float(hi);
}
__device__ __forceinline__ ull fma2(ull a, ull b, ull c) {
    ull r; asm("fma.rn.f32x2 %0, %1, %2, %3;" : "=l"(r) : "l"(a), "l"(b), "l"(c)); return r;
}
__device__ __forceinline__ ull mul2(ull a, ull b) {
    ull r; asm("mul.rn.f32x2 %0, %1, %2;" : "=l"(r) : "l"(a), "l"(b)); return r;
}

__device__ __forceinline__ float2 cmulf(float2 a, float2 b) {
    return make_float2(fmaf(a.x, b.x, -a.y * b.y), fmaf(a.x, b.y, a.y * b.x));
}
__device__ __forceinline__ int rotl12(int s, int r) {
    return ((s << r) | (s >> (12 - r))) & 0xFFF;
}

struct Sm {
    ull    xch1[DIMS];       // 32KB: T1 tiles (per-warp 512) / image buffer
    ull    xch2[DIMS];       // 32KB: T2 exchange
    float2 tab[16];
    float2 csT[2][6][12];
    float2 uvT[2][6][12];
    float  aS[2][6][12];
    float  ang[12];
    float  red[8 * 12];
    float  cwS[108];
    float  cbS[12];
};

template<int M>
__device__ __forceinline__ void ry_liftp(ull* amp, float2 uvv) {
    const ull U  = pk2(uvv.x, uvv.x);
    const ull Vv = pk2(uvv.y, uvv.y);
#pragma unroll
    for (int k = 0; k < V; k++) {
        if (!(k & M)) {
            ull a = amp[k], b = amp[k | M];
            a = fma2(U, b, a);
            b = fma2(Vv, a, b);
            a = fma2(U, b, a);
            amp[k] = a; amp[k | M] = b;
        }
    }
}

__device__ __forceinline__ void reduce12(Sm& sm, float* part, int t, int lane,
                                         float scale, bool addBias) {
#pragma unroll
    for (int j = 0; j < QW; j++) {
        float v = part[j];
        v += __shfl_down_sync(0xffffffffu, v, 16);
        v += __shfl_down_sync(0xffffffffu, v, 8);
        v += __shfl_down_sync(0xffffffffu, v, 4);
        v += __shfl_down_sync(0xffffffffu, v, 2);
        v += __shfl_down_sync(0xffffffffu, v, 1);
        if (lane == 0) sm.red[(t >> 5) * QW + j] = v;
    }
    __syncthreads();
    if (t < QW) {
        float v = 0.f;
#pragma unroll
        for (int w = 0; w < 8; w++) v += sm.red[w * QW + t];
        v *= scale;
        if (addBias) v += sm.cbS[t];
        sm.ang[t] = v;
    }
    __syncthreads();
}

template<int LAY, int R, bool ADDI, bool FIRST>
__device__ __forceinline__ void do_group(Sm& sm, ull* amp, const float* aSp,
                                         const float2* uv, int t) {
    const int lane = t & 31, w = t >> 5;
    const int l16 = lane & 15, h = (lane >> 4) & 1;

    // ---- tab build (16 entries over k bits; kk CZ parity folded) ----
    if (t < 16) {
        int k = t, km = 0;
        float ph = 0.f;
#pragma unroll
        for (int i = 0; i < 4; i++) {
            const int wi = 11 - layK(LAY, i);
            float a = aSp[wi] + (ADDI ? sm.ang[wi] : 0.f);
            ph += a * ((float)((k >> i) & 1) - 0.5f);
            km |= ((k >> i) & 1) << layK(LAY, i);
        }
        int par = __popc(km & rotl12(km, R)) & 1;
        float sv, cv; __sincosf(ph, &sv, &cv);
        float sg = par ? -1.f : 1.f;
        sm.tab[k] = make_float2(cv * sg, sv * sg);
    }

    // ---- per-thread phase (8 t bits), tt parity, cross mask ----
    float ph = 0.f; int sB = 0;
#pragma unroll
    for (int i = 0; i < 5; i++) {
        const int wi = 11 - layL(LAY, i);
        float a = aSp[wi] + (ADDI ? sm.ang[wi] : 0.f);
        int bit = (t >> i) & 1;
        ph += a * ((float)bit - 0.5f);
        sB |= bit << layL(LAY, i);
    }
#pragma unroll
    for (int i = 0; i < 3; i++) {
        const int wi = 11 - layW(LAY, i);
        float a = aSp[wi] + (ADDI ? sm.ang[wi] : 0.f);
        int bit = (t >> (5 + i)) & 1;
        ph += a * ((float)bit - 0.5f);
        sB |= bit << layW(LAY, i);
    }
    const int ptt = __popc(sB & rotl12(sB, R)) & 1;
    int c = 0;
#pragma unroll
    for (int i = 0; i < 4; i++)
        c |= (((sB >> ((layK(LAY, i) + R) % 12)) ^ (sB >> ((layK(LAY, i) + 12 - R) % 12))) & 1) << i;
    float sv, cv; __sincosf(ph, &sv, &cv);
    if (ptt) { sv = -sv; cv = -cv; }
    const float2 et  = make_float2(cv, sv);
    const float2 net = make_float2(-cv, -sv);
    __syncthreads();   // tab ready; also fences prev group's T2 reads

    // ---- diagonal (packed complex multiply) ----
#pragma unroll
    for (int k = 0; k < V; k++) {
        float2 e = ((0x6996u >> (k & c)) & 1) ? net : et;
        float2 d = cmulf(e, sm.tab[k]);
        float ax, ay; upk2(amp[k], ax, ay);
        if (FIRST) {
            // amp = (p, 0): r = (p*dx, p*dy)
            amp[k] = mul2(pk2(ax, ax), pk2(d.x, d.y));
        } else {
            // r = (ax*dx - ay*dy, ay*dx + ax*dy)
            ull r = mul2(amp[k], pk2(d.x, d.x));
            amp[k] = fma2(pk2(ay, ax), pk2(-d.y, d.y), r);
        }
    }

    // ---- stage 1: gates on current k bits (wires 11-K[i]) ----
    ry_liftp<1>(amp, uv[11 - layK(LAY, 0)]);
    ry_liftp<2>(amp, uv[11 - layK(LAY, 1)]);
    ry_liftp<4>(amp, uv[11 - layK(LAY, 2)]);
    ry_liftp<8>(amp, uv[11 - layK(LAY, 3)]);

    // ---- T1: intra-warp 16x16 transpose (k <-> lane bits 0-3) ----
    {
        ull* tile = sm.xch1 + w * 512 + h * 256;
#pragma unroll
        for (int k = 0; k < V; k++) tile[l16 * 16 + (k ^ l16)] = amp[k];
        __syncwarp();
#pragma unroll
        for (int k = 0; k < V; k++) amp[k] = tile[k * 16 + (l16 ^ k)];
        __syncwarp();
    }

    // ---- stage 2: wires 11-L[i], i<4 ----
    ry_liftp<1>(amp, uv[11 - layL(LAY, 0)]);
    ry_liftp<2>(amp, uv[11 - layL(LAY, 1)]);
    ry_liftp<4>(amp, uv[11 - layL(LAY, 2)]);
    ry_liftp<8>(amp, uv[11 - layL(LAY, 3)]);

    // ---- T2: cross-warp exchange (k <-> {lane4, warp bits}) ----
    {
        const int X = h | (w << 1);
#pragma unroll
        for (int k = 0; k < V; k++) sm.xch2[X * 256 + l16 * 16 + (k ^ l16)] = amp[k];
        __syncthreads();
#pragma unroll
        for (int k = 0; k < V; k++) amp[k] = sm.xch2[k * 256 + l16 * 16 + (X ^ l16)];
    }

    // ---- stage 3: wires 11-L[4], 11-W[0..2] ----
    ry_liftp<1>(amp, uv[11 - layL(LAY, 4)]);
    ry_liftp<2>(amp, uv[11 - layW(LAY, 0)]);
    ry_liftp<4>(amp, uv[11 - layW(LAY, 1)]);
    ry_liftp<8>(amp, uv[11 - layW(LAY, 2)]);
}

__global__ void __launch_bounds__(NT, 2) qiddm_kernel(
    const float* __restrict__ x, const float* __restrict__ conv_w,
    const float* __restrict__ conv_b, const float* __restrict__ w1,
    const float* __restrict__ lin_w, const float* __restrict__ lin_b,
    float* __restrict__ out)
{
    __shared__ Sm sm;
    const int t    = threadIdx.x;
    const int lane = t & 31;
    const int b    = blockIdx.x;

    // ---------------- weight tables ----------------
    if (t < 144) {
        int idx = t;
        int n = idx / 72, r = idx % 72, g = r / 12, w = r % 12;
        int i = g >> 1, l = g & 1;
        int base = (((n * 3 + i) * 2 + l) * 12 + w) * 3;
        float th = w1[base + 1];
        float svv, cvv; __sincosf(0.5f * th, &svv, &cvv);
        sm.csT[n][g][w] = make_float2(cvv, svv);
        sm.uvT[n][g][w] = make_float2(-__tanf(0.25f * th), svv);
        float a = w1[base + 0];
        if (g > 0) {
            int ip = (g - 1) >> 1, lp = (g - 1) & 1;
            a += w1[(((n * 3 + ip) * 2 + lp) * 12 + w) * 3 + 2];
        }
        sm.aS[n][g][w] = a;
    }
    if (t < 108) sm.cwS[t] = conv_w[t];
    if (t < 12)  sm.cbS[t] = conv_b[t];

    float* img = (float*)sm.xch1;
    const float* xb = x + (size_t)b * 1024;
    for (int i = t; i < 1024; i += NT) img[i] = xb[i];
    __syncthreads();

    // ---------------- conv 3x3 s2 p1 + global avg pool (1 pixel/thread) ----------------
    {
        float acc[QW];
#pragma unroll
        for (int cch = 0; cch < QW; cch++) acc[cch] = 0.f;
        const int oh = t >> 4, ow = t & 15;
#pragma unroll
        for (int kh = 0; kh < 3; kh++) {
            int r2 = 2 * oh + kh - 1;
            if ((unsigned)r2 < 32u) {
#pragma unroll
                for (int kw = 0; kw < 3; kw++) {
                    int c2 = 2 * ow + kw - 1;
                    if ((unsigned)c2 < 32u) {
                        float v = img[r2 * 32 + c2];
#pragma unroll
                        for (int cch = 0; cch < QW; cch++)
                            acc[cch] = fmaf(sm.cwS[cch * 9 + kh * 3 + kw], v, acc[cch]);
                    }
                }
            }
        }
        __syncthreads();
        reduce12(sm, acc, t, lane, 1.f / 256.f, true);
    }

    // ---------------- circuit blocks ----------------
    ull amp[V];
    for (int n = 0; n < 2; n++) {
        // g=0 skipped: diag on |0> = global phase; 12 RYs on |0> = real product state (layout A)
        const float2* cs0 = sm.csT[n][0];
        // thread factor: lane bit i -> wire 7-i ; warp bit i -> wire 2-i
        float tpp = 1.f;
#pragma unroll
        for (int i = 0; i < 5; i++) tpp *= ((t >> i) & 1) ? cs0[7 - i].y : cs0[7 - i].x;
#pragma unroll
        for (int i = 0; i < 3; i++) tpp *= ((t >> (5 + i)) & 1) ? cs0[2 - i].y : cs0[2 - i].x;
        // k factor: k bit i -> wire 11-i
#pragma unroll
        for (int k = 0; k < V; k++) {
            float p = tpp;
            p *= (k & 1) ? cs0[11].y : cs0[11].x;
            p *= (k & 2) ? cs0[10].y : cs0[10].x;
            p *= (k & 4) ? cs0[9].y  : cs0[9].x;
            p *= (k & 8) ? cs0[8].y  : cs0[8].x;
            amp[k] = pk2(p, 0.f);
        }

        // groups g=1..5: layouts A,B,C,A,B ; R = CZ ring of prev sublayer ; enc at g=2,4
        do_group<0, 1, false, true >(sm, amp, sm.aS[n][1], sm.uvT[n][1], t);
        do_group<1, 2, true,  false>(sm, amp, sm.aS[n][2], sm.uvT[n][2], t);
        do_group<2, 1, false, false>(sm, amp, sm.aS[n][3], sm.uvT[n][3], t);
        do_group<0, 2, true,  false>(sm, amp, sm.aS[n][4], sm.uvT[n][4], t);
        do_group<1, 1, false, false>(sm, amp, sm.aS[n][5], sm.uvT[n][5], t);

        // ---- measurement in layout C: k bit i -> wire 7-i,
        //      lane bits -> wires {3,2,1,0,11}, warp bits -> wires {10,9,8} ----
        {
            float S = 0.f, q0 = 0.f, q1 = 0.f, q2 = 0.f, q3 = 0.f;
#pragma unroll
            for (int k = 0; k < V; k++) {
                float ax, ay; upk2(amp[k], ax, ay);
                float pr = fmaf(ax, ax, ay * ay);
                S += pr;
                q0 += (k & 1) ? -pr : pr;
                q1 += (k & 2) ? -pr : pr;
                q2 += (k & 4) ? -pr : pr;
                q3 += (k & 8) ? -pr : pr;
            }
            float part[QW];
            part[7] = q0; part[6] = q1; part[5] = q2; part[4] = q3;
            part[3]  = (t & 1)   ? -S : S;   // lane0 -> wire 3
            part[2]  = (t & 2)   ? -S : S;   // lane1 -> wire 2
            part[1]  = (t & 4)   ? -S : S;   // lane2 -> wire 1
            part[0]  = (t & 8)   ? -S : S;   // lane3 -> wire 0
            part[11] = (t & 16)  ? -S : S;   // lane4 -> wire 11
            part[10] = (t & 32)  ? -S : S;   // warp0 -> wire 10
            part[9]  = (t & 64)  ? -S : S;   // warp1 -> wire 9
            part[8]  = (t & 128) ? -S : S;   // warp2 -> wire 8
            __syncthreads();
            reduce12(sm, part, t, lane, 1.f, false);
        }
    }

    // ---------------- linear head ----------------
#pragma unroll
    for (int q = 0; q < 4; q++) {
        int m = t + q * NT;
        float acc = lin_b[m];
#pragma unroll
        for (int j = 0; j < QW; j++) acc = fmaf(sm.ang[j], lin_w[m * 12 + j], acc);
        out[(size_t)b * 1024 + m] = acc;
    }
}

extern "C" void kernel_launch(void* const* d_in, const int* in_sizes, int n_in,
                              void* d_out, int out_size) {
    const float* x      = (const float*)d_in[0];
    const float* conv_w = (const float*)d_in[1];
    const float* conv_b = (const float*)d_in[2];
    const float* w1     = (const float*)d_in[3];
    const float* lin_w  = (const float*)d_in[4];
    const float* lin_b  = (const float*)d_in[5];
    float* out = (float*)d_out;
    int B = in_sizes[0] / 1024;
    qiddm_kernel<<<B, NT>>>(x, conv_w, conv_b, w1, lin_w, lin_b, out);
}